// round 4
// baseline (speedup 1.0000x reference)
#include <cuda_runtime.h>

#define NN   50000
#define IN_F 256
#define AD   128
#define NH   8
#define NE   1600000

// Scratch: q/k projections + per-(node,head) softmax sums
__device__ float g_q[(size_t)NN * AD];      // 25.6 MB
__device__ float g_k[(size_t)NN * AD];      // 25.6 MB
__device__ float g_sum[NN * NH];            // 1.6 MB

// ---------------------------------------------------------------------------
// Packed f32x2 helpers (Blackwell: fma.rn.f32x2 doubles FP32 FMA throughput;
// only reachable via PTX — ptxas never auto-fuses)
// ---------------------------------------------------------------------------
__device__ __forceinline__ unsigned long long pack2(float lo, float hi) {
    unsigned long long r;
    asm("mov.b64 %0, {%1, %2};" : "=l"(r) : "f"(lo), "f"(hi));
    return r;
}
__device__ __forceinline__ void fma2(unsigned long long& c,
                                     unsigned long long a,
                                     unsigned long long b) {
    asm("fma.rn.f32x2 %0, %1, %2, %0;" : "+l"(c) : "l"(a), "l"(b));
}

// ---------------------------------------------------------------------------
__global__ void zero_kernel() {
    int i = blockIdx.x * blockDim.x + threadIdx.x;
    if (i < NN * NH) g_sum[i] = 0.0f;
}

// ---------------------------------------------------------------------------
// Projection GEMM: out[n, a] = sum_i hi[n,i] * W[a,i] + bias[a]
// Tile M=64 x N=128, K-chunk=32. 256 threads, 4x8 microtile as 16 f32x2 accs.
// which==0 -> g_q, which==1 -> g_k  (selected in DEVICE code; __device__
// symbols must not be referenced from host code)
// ---------------------------------------------------------------------------
__global__ __launch_bounds__(256) void proj_kernel(const float* __restrict__ hi,
                                                   const float* __restrict__ W,
                                                   const float* __restrict__ bias,
                                                   int which) {
    float* out = which ? g_k : g_q;
    __shared__ float a_s[32][68];    // [k][m], 272B row (16B-aligned rows)
    __shared__ float b_s[32][136];   // [k][n], 544B row (16B-aligned rows)

    const int tid = threadIdx.x;
    const int m0  = blockIdx.x * 64;
    const int tx  = tid & 15;        // n: cols tx*8 .. tx*8+7
    const int ty  = tid >> 4;        // m: rows ty*4 .. ty*4+3

    unsigned long long acc[4][4];    // [row][col-pair], pair = cols (2j,2j+1)
#pragma unroll
    for (int i = 0; i < 4; i++)
#pragma unroll
        for (int j = 0; j < 4; j++) acc[i][j] = 0ULL;

    const float4* hi4 = (const float4*)hi;   // row stride 64 float4
    const float4* W4  = (const float4*)W;    // row stride 64 float4

    const int arow = tid >> 2, aq = tid & 3;   // A loader
    const int brow = tid >> 1, bh = tid & 1;   // B loader

    for (int kc4 = 0; kc4 < 64; kc4 += 8) {    // 8 chunks of K=32
        // Load A tile 64x32 -> a_s[k][m] (transposed store)
#pragma unroll
        for (int j = 0; j < 2; j++) {
            float4 v = make_float4(0.f, 0.f, 0.f, 0.f);
            int rg = m0 + arow;
            if (rg < NN) v = hi4[(size_t)rg * 64 + kc4 + aq * 2 + j];
            int kb = (aq * 2 + j) * 4;
            a_s[kb + 0][arow] = v.x;
            a_s[kb + 1][arow] = v.y;
            a_s[kb + 2][arow] = v.z;
            a_s[kb + 3][arow] = v.w;
        }
        // Load B tile 128x32 -> b_s[k][n]
#pragma unroll
        for (int j = 0; j < 4; j++) {
            float4 v = W4[(size_t)brow * 64 + kc4 + bh * 4 + j];
            int kb = (bh * 4 + j) * 4;
            b_s[kb + 0][brow] = v.x;
            b_s[kb + 1][brow] = v.y;
            b_s[kb + 2][brow] = v.z;
            b_s[kb + 3][brow] = v.w;
        }
        __syncthreads();

#pragma unroll 8
        for (int kk = 0; kk < 32; kk++) {
            float4 av = *(const float4*)&a_s[kk][ty * 4];
            ulonglong2 b0 = *(const ulonglong2*)&b_s[kk][tx * 8];
            ulonglong2 b1 = *(const ulonglong2*)&b_s[kk][tx * 8 + 4];
            unsigned long long ad[4];
            ad[0] = pack2(av.x, av.x);
            ad[1] = pack2(av.y, av.y);
            ad[2] = pack2(av.z, av.z);
            ad[3] = pack2(av.w, av.w);
#pragma unroll
            for (int i = 0; i < 4; i++) {
                fma2(acc[i][0], ad[i], b0.x);
                fma2(acc[i][1], ad[i], b0.y);
                fma2(acc[i][2], ad[i], b1.x);
                fma2(acc[i][3], ad[i], b1.y);
            }
        }
        __syncthreads();
    }

    // Epilogue: unpack, add bias, store 2x float4 per row
    float bcol[8];
#pragma unroll
    for (int j = 0; j < 8; j++) bcol[j] = bias[tx * 8 + j];
#pragma unroll
    for (int i = 0; i < 4; i++) {
        int rg = m0 + ty * 4 + i;
        if (rg < NN) {
            float o[8];
#pragma unroll
            for (int j2 = 0; j2 < 4; j2++) {
                unsigned long long v = acc[i][j2];
                o[2 * j2]     = __int_as_float((unsigned int)v)         + bcol[2 * j2];
                o[2 * j2 + 1] = __int_as_float((unsigned int)(v >> 32)) + bcol[2 * j2 + 1];
            }
            float4* op = (float4*)&out[(size_t)rg * AD + tx * 8];
            op[0] = make_float4(o[0], o[1], o[2], o[3]);
            op[1] = make_float4(o[4], o[5], o[6], o[7]);
        }
    }
}

// ---------------------------------------------------------------------------
// Edge pass: ONE THREAD per (edge, head). 12.8M threads, exact grid.
// Per thread: 8 independent float4 gathers (MLP 8), no shuffles.
// Warp output stores are 128B contiguous. Qrw/Qrb served from smem.
// ---------------------------------------------------------------------------
__global__ __launch_bounds__(256) void edge_kernel(const float* __restrict__ radial,
                                                   const int*  __restrict__ edge,
                                                   const float* __restrict__ Qrw,
                                                   const float* __restrict__ Qrb,
                                                   float* __restrict__ att,
                                                   float* __restrict__ prods) {
    __shared__ float4 s_w[32], s_b[32];
    if (threadIdx.x < 32) {
        s_w[threadIdx.x] = ((const float4*)Qrw)[threadIdx.x];
        s_b[threadIdx.x] = ((const float4*)Qrb)[threadIdx.x];
    }
    __syncthreads();

    const int idx = blockIdx.x * 256 + threadIdx.x;   // NE*NH = 50000*256 exactly
    const int e = idx >> 3;
    const int h = idx & 7;

    const int src = edge[e];
    const int dst = edge[NE + e];
    const float r = radial[e];

    const float4* qp = (const float4*)g_q + src * 32 + h * 4;
    const float4* kp = (const float4*)g_k + dst * 32 + h * 4;

    float p = 0.f;
#pragma unroll
    for (int c = 0; c < 4; c++) {
        float4 q = qp[c];
        float4 k = kp[c];
        float4 w = s_w[h * 4 + c];
        float4 b = s_b[h * 4 + c];
        float sx = q.x + fmaf(r, w.x, b.x);
        float sy = q.y + fmaf(r, w.y, b.y);
        float sz = q.z + fmaf(r, w.z, b.z);
        float sw = q.w + fmaf(r, w.w, b.w);
        p = fmaf(sx, k.x, p);
        p = fmaf(sy, k.y, p);
        p = fmaf(sz, k.z, p);
        p = fmaf(sw, k.w, p);
    }

    const float pr = p * 0.25f;                 // / sqrt(DK) = /4
    prods[idx] = pr;
    const float ex = __expf(pr);
    att[idx] = ex;
    atomicAdd(&g_sum[src * NH + h], ex);
}

// ---------------------------------------------------------------------------
// Normalize: att[e,h] = ex / sum[src,h]
// ---------------------------------------------------------------------------
__global__ void norm_kernel(const int* __restrict__ edge,
                            float* __restrict__ att) {
    int i = blockIdx.x * blockDim.x + threadIdx.x;
    if (i < NE * NH) {
        int e = i >> 3;
        int h = i & 7;
        att[i] = att[i] / g_sum[edge[e] * NH + h];
    }
}

// ---------------------------------------------------------------------------
extern "C" void kernel_launch(void* const* d_in, const int* in_sizes, int n_in,
                              void* d_out, int out_size) {
    const float* hi     = (const float*)d_in[0];
    const float* radial = (const float*)d_in[1];
    const float* Qw     = (const float*)d_in[2];
    const float* Qb     = (const float*)d_in[3];
    const float* Qrw    = (const float*)d_in[4];
    const float* Qrb    = (const float*)d_in[5];
    const float* Kw     = (const float*)d_in[6];
    const float* Kb     = (const float*)d_in[7];
    const int*   edge   = (const int*)d_in[8];

    float* out   = (float*)d_out;
    float* att   = out;                       // [E, H]
    float* prods = out + (size_t)NE * NH;     // [E, H]

    zero_kernel<<<(NN * NH + 255) / 256, 256>>>();
    proj_kernel<<<(NN + 63) / 64, 256>>>(hi, Qw, Qb, 0);
    proj_kernel<<<(NN + 63) / 64, 256>>>(hi, Kw, Kb, 1);
    edge_kernel<<<NE * NH / 256, 256>>>(radial, edge, Qrw, Qrb, att, prods);
    norm_kernel<<<(NE * NH + 255) / 256, 256>>>(edge, att);
}

// round 5
// speedup vs baseline: 1.5683x; 1.5683x over previous
#include <cuda_runtime.h>

#define NN   50000
#define IN_F 256
#define AD   128
#define NH   8
#define NE   1600000

// Scratch: q/k projections + per-(node,head) softmax sums
__device__ float g_q[(size_t)NN * AD];      // 25.6 MB
__device__ float g_k[(size_t)NN * AD];      // 25.6 MB
__device__ float g_sum[NN * NH];            // 1.6 MB

// ---------------------------------------------------------------------------
// Packed f32x2 helpers
// ---------------------------------------------------------------------------
__device__ __forceinline__ unsigned long long pack2(float lo, float hi) {
    unsigned long long r;
    asm("mov.b64 %0, {%1, %2};" : "=l"(r) : "f"(lo), "f"(hi));
    return r;
}
__device__ __forceinline__ void fma2(unsigned long long& c,
                                     unsigned long long a,
                                     unsigned long long b) {
    asm("fma.rn.f32x2 %0, %1, %2, %0;" : "+l"(c) : "l"(a), "l"(b));
}

// ---------------------------------------------------------------------------
__global__ void zero_kernel() {
    int i = blockIdx.x * blockDim.x + threadIdx.x;
    if (i < NN * NH) g_sum[i] = 0.0f;
}

// ---------------------------------------------------------------------------
// Projection GEMM (unchanged from R4): out[n,a] = hi[n,:] . W[a,:] + bias[a]
// which==0 -> g_q, which==1 -> g_k (device-side symbol select)
// ---------------------------------------------------------------------------
__global__ __launch_bounds__(256) void proj_kernel(const float* __restrict__ hi,
                                                   const float* __restrict__ W,
                                                   const float* __restrict__ bias,
                                                   int which) {
    float* out = which ? g_k : g_q;
    __shared__ float a_s[32][68];
    __shared__ float b_s[32][136];

    const int tid = threadIdx.x;
    const int m0  = blockIdx.x * 64;
    const int tx  = tid & 15;
    const int ty  = tid >> 4;

    unsigned long long acc[4][4];
#pragma unroll
    for (int i = 0; i < 4; i++)
#pragma unroll
        for (int j = 0; j < 4; j++) acc[i][j] = 0ULL;

    const float4* hi4 = (const float4*)hi;
    const float4* W4  = (const float4*)W;

    const int arow = tid >> 2, aq = tid & 3;
    const int brow = tid >> 1, bh = tid & 1;

    for (int kc4 = 0; kc4 < 64; kc4 += 8) {
#pragma unroll
        for (int j = 0; j < 2; j++) {
            float4 v = make_float4(0.f, 0.f, 0.f, 0.f);
            int rg = m0 + arow;
            if (rg < NN) v = hi4[(size_t)rg * 64 + kc4 + aq * 2 + j];
            int kb = (aq * 2 + j) * 4;
            a_s[kb + 0][arow] = v.x;
            a_s[kb + 1][arow] = v.y;
            a_s[kb + 2][arow] = v.z;
            a_s[kb + 3][arow] = v.w;
        }
#pragma unroll
        for (int j = 0; j < 4; j++) {
            float4 v = W4[(size_t)brow * 64 + kc4 + bh * 4 + j];
            int kb = (bh * 4 + j) * 4;
            b_s[kb + 0][brow] = v.x;
            b_s[kb + 1][brow] = v.y;
            b_s[kb + 2][brow] = v.z;
            b_s[kb + 3][brow] = v.w;
        }
        __syncthreads();

#pragma unroll 8
        for (int kk = 0; kk < 32; kk++) {
            float4 av = *(const float4*)&a_s[kk][ty * 4];
            ulonglong2 b0 = *(const ulonglong2*)&b_s[kk][tx * 8];
            ulonglong2 b1 = *(const ulonglong2*)&b_s[kk][tx * 8 + 4];
            unsigned long long ad[4];
            ad[0] = pack2(av.x, av.x);
            ad[1] = pack2(av.y, av.y);
            ad[2] = pack2(av.z, av.z);
            ad[3] = pack2(av.w, av.w);
#pragma unroll
            for (int i = 0; i < 4; i++) {
                fma2(acc[i][0], ad[i], b0.x);
                fma2(acc[i][1], ad[i], b0.y);
                fma2(acc[i][2], ad[i], b1.x);
                fma2(acc[i][3], ad[i], b1.y);
            }
        }
        __syncthreads();
    }

    float bcol[8];
#pragma unroll
    for (int j = 0; j < 8; j++) bcol[j] = bias[tx * 8 + j];
#pragma unroll
    for (int i = 0; i < 4; i++) {
        int rg = m0 + ty * 4 + i;
        if (rg < NN) {
            float o[8];
#pragma unroll
            for (int j2 = 0; j2 < 4; j2++) {
                unsigned long long v = acc[i][j2];
                o[2 * j2]     = __int_as_float((unsigned int)v)         + bcol[2 * j2];
                o[2 * j2 + 1] = __int_as_float((unsigned int)(v >> 32)) + bcol[2 * j2 + 1];
            }
            float4* op = (float4*)&out[(size_t)rg * AD + tx * 8];
            op[0] = make_float4(o[0], o[1], o[2], o[3]);
            op[1] = make_float4(o[4], o[5], o[6], o[7]);
        }
    }
}

// ---------------------------------------------------------------------------
// Edge pass: WARP per 4 EDGES. Every LDG.128 is 512B contiguous across the
// warp (perfectly coalesced); 8 independent loads in flight per thread.
// Epilogue: lane l handles (edge l>>3, head l&7) -> both 128B output stores
// are fully contiguous.
// ---------------------------------------------------------------------------
__global__ __launch_bounds__(256) void edge_kernel(const float* __restrict__ radial,
                                                   const int*  __restrict__ edge,
                                                   const float* __restrict__ Qrw,
                                                   const float* __restrict__ Qrb,
                                                   float* __restrict__ att,
                                                   float* __restrict__ prods) {
    const int lane = threadIdx.x & 31;
    const int gw   = (blockIdx.x * 256 + threadIdx.x) >> 5;  // warp id
    const int e0   = gw * 4;                                  // NE/4 warps exactly

    const float4 w4 = ((const float4*)Qrw)[lane];
    const float4 b4 = ((const float4*)Qrb)[lane];

    // Edge meta (broadcast loads: all lanes same address)
    int   src[4], dst[4];
    float rr[4];
#pragma unroll
    for (int j = 0; j < 4; j++) {
        src[j] = edge[e0 + j];
        dst[j] = edge[NE + e0 + j];
        rr[j]  = radial[e0 + j];
    }

    const float4* q4p = (const float4*)g_q;
    const float4* k4p = (const float4*)g_k;

    // Issue all 8 gathers up front (MLP 8)
    float4 qv[4], kv[4];
#pragma unroll
    for (int j = 0; j < 4; j++) {
        qv[j] = q4p[(size_t)src[j] * 32 + lane];
        kv[j] = k4p[(size_t)dst[j] * 32 + lane];
    }

    float p[4];
#pragma unroll
    for (int j = 0; j < 4; j++) {
        float sx = qv[j].x + fmaf(rr[j], w4.x, b4.x);
        float sy = qv[j].y + fmaf(rr[j], w4.y, b4.y);
        float sz = qv[j].z + fmaf(rr[j], w4.z, b4.z);
        float sw = qv[j].w + fmaf(rr[j], w4.w, b4.w);
        float t = sx * kv[j].x;
        t = fmaf(sy, kv[j].y, t);
        t = fmaf(sz, kv[j].z, t);
        t = fmaf(sw, kv[j].w, t);
        // reduce the 4 lanes of each head -> all 4 lanes hold the head sum
        t += __shfl_xor_sync(0xffffffff, t, 1);
        t += __shfl_xor_sync(0xffffffff, t, 2);
        p[j] = t;
    }

    // lane l -> edge j=l>>3, head h=l&7; head-h sum lives at lane 4h
    const int myj = lane >> 3;
    const int srcl = (lane & 7) << 2;
    float pr = 0.f;
#pragma unroll
    for (int j = 0; j < 4; j++) {
        float t = __shfl_sync(0xffffffff, p[j], srcl);
        if (j == myj) pr = t;
    }
    pr *= 0.25f;                               // / sqrt(DK)

    const int obase = e0 * NH + lane;          // contiguous 32 floats per warp
    prods[obase] = pr;
    const float ex = __expf(pr);
    att[obase] = ex;

    int mysrc = src[0];
#pragma unroll
    for (int j = 1; j < 4; j++) if (j == myj) mysrc = src[j];
    atomicAdd(&g_sum[mysrc * NH + (lane & 7)], ex);
}

// ---------------------------------------------------------------------------
// Normalize (vectorized): thread handles 4 consecutive att values
// ---------------------------------------------------------------------------
__global__ void norm_kernel(const int* __restrict__ edge,
                            float* __restrict__ att) {
    int i = blockIdx.x * blockDim.x + threadIdx.x;   // NE*NH/4 threads
    if (i < NE * NH / 4) {
        int e = i >> 1;
        int half = i & 1;
        const float4 s = *(const float4*)&g_sum[edge[e] * NH + half * 4];
        float4 a = ((float4*)att)[i];
        a.x /= s.x; a.y /= s.y; a.z /= s.z; a.w /= s.w;
        ((float4*)att)[i] = a;
    }
}

// ---------------------------------------------------------------------------
extern "C" void kernel_launch(void* const* d_in, const int* in_sizes, int n_in,
                              void* d_out, int out_size) {
    const float* hi     = (const float*)d_in[0];
    const float* radial = (const float*)d_in[1];
    const float* Qw     = (const float*)d_in[2];
    const float* Qb     = (const float*)d_in[3];
    const float* Qrw    = (const float*)d_in[4];
    const float* Qrb    = (const float*)d_in[5];
    const float* Kw     = (const float*)d_in[6];
    const float* Kb     = (const float*)d_in[7];
    const int*   edge   = (const int*)d_in[8];

    float* out   = (float*)d_out;
    float* att   = out;                       // [E, H]
    float* prods = out + (size_t)NE * NH;     // [E, H]

    zero_kernel<<<(NN * NH + 255) / 256, 256>>>();
    proj_kernel<<<(NN + 63) / 64, 256>>>(hi, Qw, Qb, 0);
    proj_kernel<<<(NN + 63) / 64, 256>>>(hi, Kw, Kb, 1);
    // NE/4 warps = 400000; 8 warps/block -> 50000 blocks (exact)
    edge_kernel<<<NE / 32, 256>>>(radial, edge, Qrw, Qrb, att, prods);
    norm_kernel<<<(NE * NH / 4 + 255) / 256, 256>>>(edge, att);
}

// round 8
// speedup vs baseline: 2.4105x; 1.5370x over previous
#include <cuda_runtime.h>
#include <cuda_bf16.h>
#include <cstdint>

#define NN   50000
#define IN_F 256
#define AD   128
#define NH   8
#define NE   1600000

// Scratch: q/k projections + per-(node,head) softmax sums
__device__ float g_q[(size_t)NN * AD];      // 25.6 MB
__device__ float g_k[(size_t)NN * AD];      // 25.6 MB
__device__ float g_sum[NN * NH];            // 1.6 MB

// ---------------------------------------------------------------------------
__global__ void zero_kernel() {
    int i = blockIdx.x * blockDim.x + threadIdx.x;
    if (i < NN * NH) g_sum[i] = 0.0f;
}

// ---------------------------------------------------------------------------
// Tensor-core helpers (mma.sync bf16, ldmatrix)
// ---------------------------------------------------------------------------
__device__ __forceinline__ void ldsm_x4(uint32_t& r0, uint32_t& r1,
                                        uint32_t& r2, uint32_t& r3,
                                        uint32_t addr) {
    asm volatile("ldmatrix.sync.aligned.m8n8.x4.shared.b16 {%0,%1,%2,%3}, [%4];"
                 : "=r"(r0), "=r"(r1), "=r"(r2), "=r"(r3) : "r"(addr));
}
// B operand: smem Wh[n][k] has k contiguous; the m16n8k16 B fragment wants
// per-thread pairs contiguous along k -> NON-transposed ldmatrix.
__device__ __forceinline__ void ldsm_x2(uint32_t& r0, uint32_t& r1,
                                        uint32_t addr) {
    asm volatile("ldmatrix.sync.aligned.m8n8.x2.shared.b16 {%0,%1}, [%2];"
                 : "=r"(r0), "=r"(r1) : "r"(addr));
}
__device__ __forceinline__ void mma_bf16(float& c0, float& c1, float& c2, float& c3,
                                         uint32_t a0, uint32_t a1, uint32_t a2, uint32_t a3,
                                         uint32_t b0, uint32_t b1) {
    asm volatile("mma.sync.aligned.m16n8k16.row.col.f32.bf16.bf16.f32 "
                 "{%0,%1,%2,%3}, {%4,%5,%6,%7}, {%8,%9}, {%0,%1,%2,%3};"
                 : "+f"(c0), "+f"(c1), "+f"(c2), "+f"(c3)
                 : "r"(a0), "r"(a1), "r"(a2), "r"(a3), "r"(b0), "r"(b1));
}

// ---------------------------------------------------------------------------
// Projection GEMM via bf16x3 split on tensor cores.
// C[m,n] = sum_k A[m,k] * W[n,k] + bias[n],  A=[50000,256], W=[128,256].
// Split x = hi(bf16) + lo(bf16); C += Ah*Bh + Ah*Bl + Al*Bh (fp32 acc).
// Block tile 128x128, K-chunk 32, 8 warps (4 M x 2 N), warp tile 32x64.
// which==0 -> g_q, which==1 -> g_k (device-side symbol select).
// ---------------------------------------------------------------------------
#define KP 40   // padded k-stride (80B rows: 16B-aligned, ldmatrix conflict-free)

__global__ __launch_bounds__(256) void proj_mma_kernel(const float* __restrict__ hi,
                                                       const float* __restrict__ W,
                                                       const float* __restrict__ bias,
                                                       int which) {
    float* out = which ? g_k : g_q;
    __shared__ __nv_bfloat16 Ah[128][KP], Al[128][KP];
    __shared__ __nv_bfloat16 Wh[128][KP], Wl[128][KP];

    const int tid  = threadIdx.x;
    const int lane = tid & 31;
    const int wid  = tid >> 5;
    const int wm   = wid & 3;            // warp M index: rows wm*32..+31
    const int wn   = wid >> 2;           // warp N index: cols wn*64..+63
    const int m0   = blockIdx.x * 128;

    float c[2][8][4];
#pragma unroll
    for (int mt = 0; mt < 2; mt++)
#pragma unroll
        for (int nt = 0; nt < 8; nt++)
#pragma unroll
            for (int i = 0; i < 4; i++) c[mt][nt][i] = 0.0f;

    const float4* hi4 = (const float4*)hi;   // row stride 64 float4
    const float4* W4  = (const float4*)W;

    // Loader mapping: 2 threads per row, each 4 float4 (16 floats)
    const int lrow = tid >> 1;
    const int lhalf = tid & 1;

    // ldmatrix source addresses (computed once; k-offset added per step)
    const int a_row = wm * 32 + (lane & 15);
    const int a_koff = (lane >> 4) * 8;
    const int b_row = wn * 64 + (lane & 7);      // +nt*8 per tile
    const int b_koff = ((lane >> 3) & 1) * 8;

    for (int kc4 = 0; kc4 < 64; kc4 += 8) {      // 8 chunks of K=32
        __syncthreads();
        // --- load + convert A tile (128 x 32) ---
        {
            int rg = m0 + lrow;
#pragma unroll
            for (int j = 0; j < 4; j++) {
                float4 v = make_float4(0.f, 0.f, 0.f, 0.f);
                if (rg < NN) v = hi4[(size_t)rg * 64 + kc4 + lhalf * 4 + j];
                int col = lhalf * 16 + j * 4;
                float xs[4] = {v.x, v.y, v.z, v.w};
#pragma unroll
                for (int t = 0; t < 2; t++) {
                    __nv_bfloat16 h0 = __float2bfloat16_rn(xs[2 * t]);
                    __nv_bfloat16 h1 = __float2bfloat16_rn(xs[2 * t + 1]);
                    __nv_bfloat16 l0 = __float2bfloat16_rn(xs[2 * t] - __bfloat162float(h0));
                    __nv_bfloat16 l1 = __float2bfloat16_rn(xs[2 * t + 1] - __bfloat162float(h1));
                    *(__nv_bfloat162*)&Ah[lrow][col + 2 * t] = __nv_bfloat162(h0, h1);
                    *(__nv_bfloat162*)&Al[lrow][col + 2 * t] = __nv_bfloat162(l0, l1);
                }
            }
        }
        // --- load + convert W tile (128 x 32) ---
        {
#pragma unroll
            for (int j = 0; j < 4; j++) {
                float4 v = W4[(size_t)lrow * 64 + kc4 + lhalf * 4 + j];
                int col = lhalf * 16 + j * 4;
                float xs[4] = {v.x, v.y, v.z, v.w};
#pragma unroll
                for (int t = 0; t < 2; t++) {
                    __nv_bfloat16 h0 = __float2bfloat16_rn(xs[2 * t]);
                    __nv_bfloat16 h1 = __float2bfloat16_rn(xs[2 * t + 1]);
                    __nv_bfloat16 l0 = __float2bfloat16_rn(xs[2 * t] - __bfloat162float(h0));
                    __nv_bfloat16 l1 = __float2bfloat16_rn(xs[2 * t + 1] - __bfloat162float(h1));
                    *(__nv_bfloat162*)&Wh[lrow][col + 2 * t] = __nv_bfloat162(h0, h1);
                    *(__nv_bfloat162*)&Wl[lrow][col + 2 * t] = __nv_bfloat162(l0, l1);
                }
            }
        }
        __syncthreads();

        // --- mma phase: 2 k-steps of 16 ---
#pragma unroll
        for (int ks = 0; ks < 2; ks++) {
            const int k0 = ks * 16;
            uint32_t ah[2][4], al[2][4];
#pragma unroll
            for (int mt = 0; mt < 2; mt++) {
                uint32_t addr_h = (uint32_t)__cvta_generic_to_shared(
                    &Ah[a_row + mt * 16][k0 + a_koff]);
                ldsm_x4(ah[mt][0], ah[mt][1], ah[mt][2], ah[mt][3], addr_h);
                uint32_t addr_l = (uint32_t)__cvta_generic_to_shared(
                    &Al[a_row + mt * 16][k0 + a_koff]);
                ldsm_x4(al[mt][0], al[mt][1], al[mt][2], al[mt][3], addr_l);
            }
#pragma unroll
            for (int nt = 0; nt < 8; nt++) {
                uint32_t bh0, bh1, bl0, bl1;
                uint32_t baddr_h = (uint32_t)__cvta_generic_to_shared(
                    &Wh[b_row + nt * 8][k0 + b_koff]);
                ldsm_x2(bh0, bh1, baddr_h);
                uint32_t baddr_l = (uint32_t)__cvta_generic_to_shared(
                    &Wl[b_row + nt * 8][k0 + b_koff]);
                ldsm_x2(bl0, bl1, baddr_l);
#pragma unroll
                for (int mt = 0; mt < 2; mt++) {
                    mma_bf16(c[mt][nt][0], c[mt][nt][1], c[mt][nt][2], c[mt][nt][3],
                             ah[mt][0], ah[mt][1], ah[mt][2], ah[mt][3], bh0, bh1);
                    mma_bf16(c[mt][nt][0], c[mt][nt][1], c[mt][nt][2], c[mt][nt][3],
                             ah[mt][0], ah[mt][1], ah[mt][2], ah[mt][3], bl0, bl1);
                    mma_bf16(c[mt][nt][0], c[mt][nt][1], c[mt][nt][2], c[mt][nt][3],
                             al[mt][0], al[mt][1], al[mt][2], al[mt][3], bh0, bh1);
                }
            }
        }
    }

    // --- epilogue: add bias, store fp32 ---
#pragma unroll
    for (int nt = 0; nt < 8; nt++) {
        const int col = wn * 64 + nt * 8 + (lane & 3) * 2;
        const float b0 = __ldg(&bias[col]);
        const float b1 = __ldg(&bias[col + 1]);
#pragma unroll
        for (int mt = 0; mt < 2; mt++) {
            const int r0 = m0 + wm * 32 + mt * 16 + (lane >> 2);
            if (r0 < NN) {
                float2 v0 = make_float2(c[mt][nt][0] + b0, c[mt][nt][1] + b1);
                *(float2*)&out[(size_t)r0 * AD + col] = v0;
            }
            const int r1 = r0 + 8;
            if (r1 < NN) {
                float2 v1 = make_float2(c[mt][nt][2] + b0, c[mt][nt][3] + b1);
                *(float2*)&out[(size_t)r1 * AD + col] = v1;
            }
        }
    }
}

// ---------------------------------------------------------------------------
// Edge pass (unchanged from R5): warp per 4 edges, fully coalesced gathers.
// ---------------------------------------------------------------------------
__global__ __launch_bounds__(256) void edge_kernel(const float* __restrict__ radial,
                                                   const int*  __restrict__ edge,
                                                   const float* __restrict__ Qrw,
                                                   const float* __restrict__ Qrb,
                                                   float* __restrict__ att,
                                                   float* __restrict__ prods) {
    const int lane = threadIdx.x & 31;
    const int gw   = (blockIdx.x * 256 + threadIdx.x) >> 5;
    const int e0   = gw * 4;

    const float4 w4 = ((const float4*)Qrw)[lane];
    const float4 b4 = ((const float4*)Qrb)[lane];

    int   src[4], dst[4];
    float rr[4];
#pragma unroll
    for (int j = 0; j < 4; j++) {
        src[j] = edge[e0 + j];
        dst[j] = edge[NE + e0 + j];
        rr[j]  = radial[e0 + j];
    }

    const float4* q4p = (const float4*)g_q;
    const float4* k4p = (const float4*)g_k;

    float4 qv[4], kv[4];
#pragma unroll
    for (int j = 0; j < 4; j++) {
        qv[j] = q4p[(size_t)src[j] * 32 + lane];
        kv[j] = k4p[(size_t)dst[j] * 32 + lane];
    }

    float p[4];
#pragma unroll
    for (int j = 0; j < 4; j++) {
        float sx = qv[j].x + fmaf(rr[j], w4.x, b4.x);
        float sy = qv[j].y + fmaf(rr[j], w4.y, b4.y);
        float sz = qv[j].z + fmaf(rr[j], w4.z, b4.z);
        float sw = qv[j].w + fmaf(rr[j], w4.w, b4.w);
        float t = sx * kv[j].x;
        t = fmaf(sy, kv[j].y, t);
        t = fmaf(sz, kv[j].z, t);
        t = fmaf(sw, kv[j].w, t);
        t += __shfl_xor_sync(0xffffffff, t, 1);
        t += __shfl_xor_sync(0xffffffff, t, 2);
        p[j] = t;
    }

    const int myj = lane >> 3;
    const int srcl = (lane & 7) << 2;
    float pr = 0.f;
#pragma unroll
    for (int j = 0; j < 4; j++) {
        float t = __shfl_sync(0xffffffff, p[j], srcl);
        if (j == myj) pr = t;
    }
    pr *= 0.25f;

    const int obase = e0 * NH + lane;
    prods[obase] = pr;
    const float ex = __expf(pr);
    att[obase] = ex;

    int mysrc = src[0];
#pragma unroll
    for (int j = 1; j < 4; j++) if (j == myj) mysrc = src[j];
    atomicAdd(&g_sum[mysrc * NH + (lane & 7)], ex);
}

// ---------------------------------------------------------------------------
__global__ void norm_kernel(const int* __restrict__ edge,
                            float* __restrict__ att) {
    int i = blockIdx.x * blockDim.x + threadIdx.x;
    if (i < NE * NH / 4) {
        int e = i >> 1;
        int half = i & 1;
        const float4 s = *(const float4*)&g_sum[edge[e] * NH + half * 4];
        float4 a = ((float4*)att)[i];
        a.x /= s.x; a.y /= s.y; a.z /= s.z; a.w /= s.w;
        ((float4*)att)[i] = a;
    }
}

// ---------------------------------------------------------------------------
extern "C" void kernel_launch(void* const* d_in, const int* in_sizes, int n_in,
                              void* d_out, int out_size) {
    const float* hi     = (const float*)d_in[0];
    const float* radial = (const float*)d_in[1];
    const float* Qw     = (const float*)d_in[2];
    const float* Qb     = (const float*)d_in[3];
    const float* Qrw    = (const float*)d_in[4];
    const float* Qrb    = (const float*)d_in[5];
    const float* Kw     = (const float*)d_in[6];
    const float* Kb     = (const float*)d_in[7];
    const int*   edge   = (const int*)d_in[8];

    float* out   = (float*)d_out;
    float* att   = out;                       // [E, H]
    float* prods = out + (size_t)NE * NH;     // [E, H]

    zero_kernel<<<(NN * NH + 255) / 256, 256>>>();
    proj_mma_kernel<<<(NN + 127) / 128, 256>>>(hi, Qw, Qb, 0);
    proj_mma_kernel<<<(NN + 127) / 128, 256>>>(hi, Kw, Kb, 1);
    edge_kernel<<<NE / 32, 256>>>(radial, edge, Qrw, Qrb, att, prods);
    norm_kernel<<<(NE * NH / 4 + 255) / 256, 256>>>(edge, att);
}

// round 9
// speedup vs baseline: 3.0660x; 1.2719x over previous
#include <cuda_runtime.h>
#include <cuda_bf16.h>
#include <cuda_fp16.h>
#include <cstdint>

#define NN   50000
#define IN_F 256
#define AD   128
#define NH   8
#define NE   1600000

// Scratch: q/k projections (fp16) + per-(node,head) softmax sums
__device__ __half g_qh[(size_t)NN * AD];    // 12.8 MB
__device__ __half g_kh[(size_t)NN * AD];    // 12.8 MB
__device__ float  g_sum[NN * NH];           // 1.6 MB

// ---------------------------------------------------------------------------
__global__ void zero_kernel() {
    int i = blockIdx.x * blockDim.x + threadIdx.x;
    if (i < NN * NH) g_sum[i] = 0.0f;
}

// ---------------------------------------------------------------------------
// Tensor-core helpers (mma.sync bf16, ldmatrix)
// ---------------------------------------------------------------------------
__device__ __forceinline__ void ldsm_x4(uint32_t& r0, uint32_t& r1,
                                        uint32_t& r2, uint32_t& r3,
                                        uint32_t addr) {
    asm volatile("ldmatrix.sync.aligned.m8n8.x4.shared.b16 {%0,%1,%2,%3}, [%4];"
                 : "=r"(r0), "=r"(r1), "=r"(r2), "=r"(r3) : "r"(addr));
}
__device__ __forceinline__ void ldsm_x2(uint32_t& r0, uint32_t& r1,
                                        uint32_t addr) {
    asm volatile("ldmatrix.sync.aligned.m8n8.x2.shared.b16 {%0,%1}, [%2];"
                 : "=r"(r0), "=r"(r1) : "r"(addr));
}
__device__ __forceinline__ void mma_bf16(float& c0, float& c1, float& c2, float& c3,
                                         uint32_t a0, uint32_t a1, uint32_t a2, uint32_t a3,
                                         uint32_t b0, uint32_t b1) {
    asm volatile("mma.sync.aligned.m16n8k16.row.col.f32.bf16.bf16.f32 "
                 "{%0,%1,%2,%3}, {%4,%5,%6,%7}, {%8,%9}, {%0,%1,%2,%3};"
                 : "+f"(c0), "+f"(c1), "+f"(c2), "+f"(c3)
                 : "r"(a0), "r"(a1), "r"(a2), "r"(a3), "r"(b0), "r"(b1));
}

// ---------------------------------------------------------------------------
// Projection GEMM via bf16x3 split on tensor cores, software-pipelined.
// gridDim.y=2: y==0 -> Q (g_qh), y==1 -> K (g_kh). fp16 output.
// Block tile 128x128, K-chunk 32, 8 warps (4 M x 2 N), warp tile 32x64.
// Pipeline: prefetch chunk i+1 global->regs during chunk i's mma phase.
// ---------------------------------------------------------------------------
#define KP 40   // padded k-stride (80B rows)

__global__ __launch_bounds__(256) void proj_mma_kernel(const float* __restrict__ hi,
                                                       const float* __restrict__ Qw,
                                                       const float* __restrict__ Qb,
                                                       const float* __restrict__ Kw,
                                                       const float* __restrict__ Kb) {
    const int which = blockIdx.y;
    const float* W    = which ? Kw : Qw;
    const float* bias = which ? Kb : Qb;
    __half* out = which ? g_kh : g_qh;

    __shared__ __nv_bfloat16 Ah[128][KP], Al[128][KP];
    __shared__ __nv_bfloat16 Wh[128][KP], Wl[128][KP];

    const int tid  = threadIdx.x;
    const int lane = tid & 31;
    const int wid  = tid >> 5;
    const int wm   = wid & 3;
    const int wn   = wid >> 2;
    const int m0   = blockIdx.x * 128;

    float c[2][8][4];
#pragma unroll
    for (int mt = 0; mt < 2; mt++)
#pragma unroll
        for (int nt = 0; nt < 8; nt++)
#pragma unroll
            for (int i = 0; i < 4; i++) c[mt][nt][i] = 0.0f;

    const float4* hi4 = (const float4*)hi;
    const float4* W4  = (const float4*)W;

    const int lrow  = tid >> 1;
    const int lhalf = tid & 1;
    const int arow_g = m0 + lrow;

    const int a_row  = wm * 32 + (lane & 15);
    const int a_koff = (lane >> 4) * 8;
    const int b_row  = wn * 64 + (lane & 7);
    const int b_koff = ((lane >> 3) & 1) * 8;

    float4 pa[4], pw[4];   // prefetch registers

    // ---- prologue: load chunk 0 ----
#pragma unroll
    for (int j = 0; j < 4; j++) {
        pa[j] = make_float4(0.f, 0.f, 0.f, 0.f);
        if (arow_g < NN) pa[j] = hi4[(size_t)arow_g * 64 + lhalf * 4 + j];
        pw[j] = W4[(size_t)lrow * 64 + lhalf * 4 + j];
    }

    for (int ch = 0; ch < 8; ch++) {
        // ---- convert + store prefetched regs to smem ----
#pragma unroll
        for (int j = 0; j < 4; j++) {
            int col = lhalf * 16 + j * 4;
            float xs[4] = {pa[j].x, pa[j].y, pa[j].z, pa[j].w};
            float ws[4] = {pw[j].x, pw[j].y, pw[j].z, pw[j].w};
#pragma unroll
            for (int t = 0; t < 2; t++) {
                __nv_bfloat16 h0 = __float2bfloat16_rn(xs[2 * t]);
                __nv_bfloat16 h1 = __float2bfloat16_rn(xs[2 * t + 1]);
                __nv_bfloat16 l0 = __float2bfloat16_rn(xs[2 * t] - __bfloat162float(h0));
                __nv_bfloat16 l1 = __float2bfloat16_rn(xs[2 * t + 1] - __bfloat162float(h1));
                *(__nv_bfloat162*)&Ah[lrow][col + 2 * t] = __nv_bfloat162(h0, h1);
                *(__nv_bfloat162*)&Al[lrow][col + 2 * t] = __nv_bfloat162(l0, l1);
                __nv_bfloat16 wh0 = __float2bfloat16_rn(ws[2 * t]);
                __nv_bfloat16 wh1 = __float2bfloat16_rn(ws[2 * t + 1]);
                __nv_bfloat16 wl0 = __float2bfloat16_rn(ws[2 * t] - __bfloat162float(wh0));
                __nv_bfloat16 wl1 = __float2bfloat16_rn(ws[2 * t + 1] - __bfloat162float(wh1));
                *(__nv_bfloat162*)&Wh[lrow][col + 2 * t] = __nv_bfloat162(wh0, wh1);
                *(__nv_bfloat162*)&Wl[lrow][col + 2 * t] = __nv_bfloat162(wl0, wl1);
            }
        }
        __syncthreads();

        // ---- prefetch next chunk (LDGs in flight during mma) ----
        if (ch < 7) {
            const int kc4 = (ch + 1) * 8;
#pragma unroll
            for (int j = 0; j < 4; j++) {
                pa[j] = make_float4(0.f, 0.f, 0.f, 0.f);
                if (arow_g < NN) pa[j] = hi4[(size_t)arow_g * 64 + kc4 + lhalf * 4 + j];
                pw[j] = W4[(size_t)lrow * 64 + kc4 + lhalf * 4 + j];
            }
        }

        // ---- mma phase: 2 k-steps of 16 ----
#pragma unroll
        for (int ks = 0; ks < 2; ks++) {
            const int k0 = ks * 16;
            uint32_t ah[2][4], al[2][4];
#pragma unroll
            for (int mt = 0; mt < 2; mt++) {
                uint32_t addr_h = (uint32_t)__cvta_generic_to_shared(
                    &Ah[a_row + mt * 16][k0 + a_koff]);
                ldsm_x4(ah[mt][0], ah[mt][1], ah[mt][2], ah[mt][3], addr_h);
                uint32_t addr_l = (uint32_t)__cvta_generic_to_shared(
                    &Al[a_row + mt * 16][k0 + a_koff]);
                ldsm_x4(al[mt][0], al[mt][1], al[mt][2], al[mt][3], addr_l);
            }
#pragma unroll
            for (int nt = 0; nt < 8; nt++) {
                uint32_t bh0, bh1, bl0, bl1;
                uint32_t baddr_h = (uint32_t)__cvta_generic_to_shared(
                    &Wh[b_row + nt * 8][k0 + b_koff]);
                ldsm_x2(bh0, bh1, baddr_h);
                uint32_t baddr_l = (uint32_t)__cvta_generic_to_shared(
                    &Wl[b_row + nt * 8][k0 + b_koff]);
                ldsm_x2(bl0, bl1, baddr_l);
#pragma unroll
                for (int mt = 0; mt < 2; mt++) {
                    mma_bf16(c[mt][nt][0], c[mt][nt][1], c[mt][nt][2], c[mt][nt][3],
                             ah[mt][0], ah[mt][1], ah[mt][2], ah[mt][3], bh0, bh1);
                    mma_bf16(c[mt][nt][0], c[mt][nt][1], c[mt][nt][2], c[mt][nt][3],
                             ah[mt][0], ah[mt][1], ah[mt][2], ah[mt][3], bl0, bl1);
                    mma_bf16(c[mt][nt][0], c[mt][nt][1], c[mt][nt][2], c[mt][nt][3],
                             al[mt][0], al[mt][1], al[mt][2], al[mt][3], bh0, bh1);
                }
            }
        }
        __syncthreads();   // mma reads done before next chunk's smem store
    }

    // ---- epilogue: add bias, store fp16 ----
#pragma unroll
    for (int nt = 0; nt < 8; nt++) {
        const int col = wn * 64 + nt * 8 + (lane & 3) * 2;
        const float b0 = __ldg(&bias[col]);
        const float b1 = __ldg(&bias[col + 1]);
#pragma unroll
        for (int mt = 0; mt < 2; mt++) {
            const int r0 = m0 + wm * 32 + mt * 16 + (lane >> 2);
            if (r0 < NN) {
                *(__half2*)&out[(size_t)r0 * AD + col] =
                    __floats2half2_rn(c[mt][nt][0] + b0, c[mt][nt][1] + b1);
            }
            const int r1 = r0 + 8;
            if (r1 < NN) {
                *(__half2*)&out[(size_t)r1 * AD + col] =
                    __floats2half2_rn(c[mt][nt][2] + b0, c[mt][nt][3] + b1);
            }
        }
    }
}

// ---------------------------------------------------------------------------
// Edge pass: warp per 4 edges, fp16 q/k gathers (8B/lane, 256B/warp per side).
// lane l owns features 4l..4l+3; head h = lane>>2 over lanes 4h..4h+3.
// ---------------------------------------------------------------------------
__global__ __launch_bounds__(256) void edge_kernel(const float* __restrict__ radial,
                                                   const int*  __restrict__ edge,
                                                   const float* __restrict__ Qrw,
                                                   const float* __restrict__ Qrb,
                                                   float* __restrict__ att,
                                                   float* __restrict__ prods) {
    const int lane = threadIdx.x & 31;
    const int gw   = (blockIdx.x * 256 + threadIdx.x) >> 5;
    const int e0   = gw * 4;

    const float4 w4 = ((const float4*)Qrw)[lane];
    const float4 b4 = ((const float4*)Qrb)[lane];

    int   src[4], dst[4];
    float rr[4];
#pragma unroll
    for (int j = 0; j < 4; j++) {
        src[j] = edge[e0 + j];
        dst[j] = edge[NE + e0 + j];
        rr[j]  = radial[e0 + j];
    }

    // 8 independent 8B gathers (4 halves each), fully coalesced per warp
    float2 qraw[4], kraw[4];
#pragma unroll
    for (int j = 0; j < 4; j++) {
        qraw[j] = *(const float2*)(g_qh + (size_t)src[j] * AD + lane * 4);
        kraw[j] = *(const float2*)(g_kh + (size_t)dst[j] * AD + lane * 4);
    }

    float p[4];
#pragma unroll
    for (int j = 0; j < 4; j++) {
        float2 q01 = __half22float2(*(__half2*)&qraw[j].x);
        float2 q23 = __half22float2(*(__half2*)&qraw[j].y);
        float2 k01 = __half22float2(*(__half2*)&kraw[j].x);
        float2 k23 = __half22float2(*(__half2*)&kraw[j].y);

        float sx = q01.x + fmaf(rr[j], w4.x, b4.x);
        float sy = q01.y + fmaf(rr[j], w4.y, b4.y);
        float sz = q23.x + fmaf(rr[j], w4.z, b4.z);
        float sw = q23.y + fmaf(rr[j], w4.w, b4.w);
        float t = sx * k01.x;
        t = fmaf(sy, k01.y, t);
        t = fmaf(sz, k23.x, t);
        t = fmaf(sw, k23.y, t);
        t += __shfl_xor_sync(0xffffffff, t, 1);
        t += __shfl_xor_sync(0xffffffff, t, 2);
        p[j] = t;
    }

    const int myj  = lane >> 3;
    const int srcl = (lane & 7) << 2;
    float pr = 0.f;
#pragma unroll
    for (int j = 0; j < 4; j++) {
        float t = __shfl_sync(0xffffffff, p[j], srcl);
        if (j == myj) pr = t;
    }
    pr *= 0.25f;

    const int obase = e0 * NH + lane;
    prods[obase] = pr;
    const float ex = __expf(pr);
    att[obase] = ex;

    int mysrc = src[0];
#pragma unroll
    for (int j = 1; j < 4; j++) if (j == myj) mysrc = src[j];
    atomicAdd(&g_sum[mysrc * NH + (lane & 7)], ex);
}

// ---------------------------------------------------------------------------
__global__ void norm_kernel(const int* __restrict__ edge,
                            float* __restrict__ att) {
    int i = blockIdx.x * blockDim.x + threadIdx.x;
    if (i < NE * NH / 4) {
        int e = i >> 1;
        int half = i & 1;
        const float4 s = *(const float4*)&g_sum[edge[e] * NH + half * 4];
        float4 a = ((float4*)att)[i];
        a.x /= s.x; a.y /= s.y; a.z /= s.z; a.w /= s.w;
        ((float4*)att)[i] = a;
    }
}

// ---------------------------------------------------------------------------
extern "C" void kernel_launch(void* const* d_in, const int* in_sizes, int n_in,
                              void* d_out, int out_size) {
    const float* hi     = (const float*)d_in[0];
    const float* radial = (const float*)d_in[1];
    const float* Qw     = (const float*)d_in[2];
    const float* Qb     = (const float*)d_in[3];
    const float* Qrw    = (const float*)d_in[4];
    const float* Qrb    = (const float*)d_in[5];
    const float* Kw     = (const float*)d_in[6];
    const float* Kb     = (const float*)d_in[7];
    const int*   edge   = (const int*)d_in[8];

    float* out   = (float*)d_out;
    float* att   = out;                       // [E, H]
    float* prods = out + (size_t)NE * NH;     // [E, H]

    zero_kernel<<<(NN * NH + 255) / 256, 256>>>();
    dim3 pg((NN + 127) / 128, 2);
    proj_mma_kernel<<<pg, 256>>>(hi, Qw, Qb, Kw, Kb);
    edge_kernel<<<NE / 32, 256>>>(radial, edge, Qrw, Qrb, att, prods);
    norm_kernel<<<(NE * NH / 4 + 255) / 256, 256>>>(edge, att);
}